// round 14
// baseline (speedup 1.0000x reference)
#include <cuda_runtime.h>
#include <math.h>
#include <stdint.h>

#define TT 128
#define NN 1000
#define EE 16000
#define FF 397
#define HH 128
#define DD 8
#define G4 512   // 4*HH
#define BM 128
#define BKT 32   // K per tile
#define PB2 20   // smem pitch in u32 (bf16 pairs): bank = (4r+c)%32, conflict-free
#define TPB2 (128*PB2)       // u32 per tile array
#define BUFU (4*TPB2)        // u32 per stage (Ah,Al,Bh,Bl)
#define KP1 416
#define KP2 128

// ---- static scratch (allocation-free rule: __device__ globals) ----
__device__ float g_Y [TT*NN*HH];
__device__ float g_H1[TT*NN*HH];
__device__ int   g_cnt  [TT*NN];
__device__ int   g_start[TT*NN];
__device__ int   g_eidx [TT*EE];
__device__ float g_pool [TT*HH];
__device__ float g_Gx   [TT*G4];
__device__ uint32_t g_W1h[HH*KP1/2], g_W1l[HH*KP1/2];
__device__ uint32_t g_W2h[HH*KP2/2], g_W2l[HH*KP2/2];

// ---- helpers ----
__device__ __forceinline__ uint32_t bf16x2_pack(float lo, float hi) {
    uint32_t r;
    asm("cvt.rn.bf16x2.f32 %0, %1, %2;" : "=r"(r) : "f"(hi), "f"(lo));
    return r;
}
// bf16 -> f32 is exact: bits << 16
__device__ __forceinline__ float bf_lo_f(uint32_t p) { return __uint_as_float(p << 16); }
__device__ __forceinline__ float bf_hi_f(uint32_t p) { return __uint_as_float(p & 0xFFFF0000u); }

__device__ __forceinline__ void mma_bf16(float* d, const uint32_t* a, const uint32_t* b) {
    asm volatile("mma.sync.aligned.m16n8k16.row.col.f32.bf16.bf16.f32 "
                 "{%0,%1,%2,%3}, {%4,%5,%6,%7}, {%8,%9}, {%0,%1,%2,%3};"
                 : "+f"(d[0]), "+f"(d[1]), "+f"(d[2]), "+f"(d[3])
                 : "r"(a[0]), "r"(a[1]), "r"(a[2]), "r"(a[3]),
                   "r"(b[0]), "r"(b[1]));
}

// ---------------- W pre-split: fp32 -> bf16 hi/lo pairs ----------------
__global__ void wsplit_kernel(const float* __restrict__ w, uint32_t* __restrict__ wh,
                              uint32_t* __restrict__ wl, int K, int Kpad) {
    int P2 = Kpad >> 1;
    int i = blockIdx.x*blockDim.x + threadIdx.x;
    if (i >= HH*P2) return;
    int r = i / P2, p = i - r*P2;
    int k0 = 2*p;
    float x0 = (k0     < K) ? w[r*K + k0]     : 0.f;
    float x1 = (k0 + 1 < K) ? w[r*K + k0 + 1] : 0.f;
    uint32_t h = bf16x2_pack(x0, x1);
    wh[i] = h;
    wl[i] = bf16x2_pack(x0 - bf_lo_f(h), x1 - bf_hi_f(h));
}

// ---------------- fused CSR build + g_pool zero: one block per timestep ----
__global__ void __launch_bounds__(1024) csr_kernel(const int* __restrict__ ei) {
    __shared__ int scnt[1024];
    __shared__ int sscan[1024];
    int t = blockIdx.x, tid = threadIdx.x;
    scnt[tid] = 0;
    if (tid < HH) g_pool[t*HH + tid] = 0.f;    // zero pool accumulator
    __syncthreads();
    const int* srcp = ei + t*2*EE;
    const int* dstp = srcp + EE;
    for (int e = tid; e < EE; e += 1024) atomicAdd(&scnt[dstp[e]], 1);
    __syncthreads();
    int v = scnt[tid];
    sscan[tid] = v;
    __syncthreads();
    for (int off = 1; off < 1024; off <<= 1) {
        int u = (tid >= off) ? sscan[tid - off] : 0;
        __syncthreads();
        sscan[tid] += u;
        __syncthreads();
    }
    int start = sscan[tid] - v;
    if (tid < NN) { g_start[t*NN + tid] = start; g_cnt[t*NN + tid] = v; }
    __syncthreads();
    scnt[tid] = start;          // reuse as cursor
    __syncthreads();
    int* eix = g_eidx + t*EE;
    for (int e = tid; e < EE; e += 1024) {
        int d = dstp[e], s = srcp[e];
        int pos = atomicAdd(&scnt[d], 1);
        eix[pos] = s;
    }
}

// ==== tensor GEMM (R9 measured-best): 512 thr, BM=128, double-buffered ====
// Per iter: LDG tile i+1 -> mma on buf i (hides LDG) -> split+STS buf i^1.
// B comes pre-split (bf16 hi/lo u32 pairs) from wsplit_kernel.
__global__ void __launch_bounds__(512, 1) gemm_mma_kernel(
    const float* __restrict__ A, const uint32_t* __restrict__ Wh,
    const uint32_t* __restrict__ Wl, const float* __restrict__ bias,
    float* __restrict__ C, int K, int Kpad)
{
    extern __shared__ uint32_t smu[];
    int tid = threadIdx.x;
    int lane = tid & 31, wid = tid >> 5;
    long m0 = (long)blockIdx.x * BM;

    int mw = (wid & 3) * 32;
    int nw = (wid >> 2) * 32;
    int r = lane >> 2, c = lane & 3;

    float acc[2][4][4];
    #pragma unroll
    for (int f = 0; f < 2; f++)
        #pragma unroll
        for (int g = 0; g < 4; g++)
            #pragma unroll
            for (int e = 0; e < 4; e++) acc[f][g][e] = 0.f;

    int srow = tid >> 2, skq = (tid & 3) * 8;
    const float* Arow = A + (m0 + srow) * (long)K;
    int P2 = Kpad >> 1;
    const uint32_t* Bh_row = Wh + srow * P2;
    const uint32_t* Bl_row = Wl + srow * P2;

    int NT = (Kpad + BKT - 1) / BKT;
    float rA[8];
    uint32_t rBh[4], rBl[4];

    auto ldg_tile = [&](int it) {
        int k0 = it * BKT;
        #pragma unroll
        for (int j = 0; j < 8; j++) {
            int k = k0 + skq + j;
            rA[j] = (k < K) ? Arow[k] : 0.f;
        }
        int bidx = (k0 >> 1) + (skq >> 1);
        #pragma unroll
        for (int j = 0; j < 4; j++) {
            rBh[j] = Bh_row[bidx + j];
            rBl[j] = Bl_row[bidx + j];
        }
    };
    auto sts_tile = [&](int buf) {
        uint32_t* sAh = smu + buf*BUFU;
        uint32_t* sAl = sAh + TPB2;
        uint32_t* sBh = sAh + 2*TPB2;
        uint32_t* sBl = sAh + 3*TPB2;
        uint32_t ha[4], la[4];
        #pragma unroll
        for (int j = 0; j < 4; j++) {
            float x0 = rA[2*j], x1 = rA[2*j+1];
            uint32_t h = bf16x2_pack(x0, x1);
            ha[j] = h;
            la[j] = bf16x2_pack(x0 - bf_lo_f(h), x1 - bf_hi_f(h));
        }
        int so = srow*PB2 + (skq >> 1);
        *(uint4*)&sAh[so] = *(uint4*)ha;
        *(uint4*)&sAl[so] = *(uint4*)la;
        *(uint4*)&sBh[so] = *(uint4*)rBh;
        *(uint4*)&sBl[so] = *(uint4*)rBl;
    };

    ldg_tile(0);
    sts_tile(0);
    __syncthreads();

    for (int it = 0; it < NT; it++) {
        int buf = it & 1;
        if (it + 1 < NT) ldg_tile(it + 1);
        {
            const uint32_t* sAh = smu + buf*BUFU;
            const uint32_t* sAl = sAh + TPB2;
            const uint32_t* sBh = sAh + 2*TPB2;
            const uint32_t* sBl = sAh + 3*TPB2;
            #pragma unroll
            for (int ks = 0; ks < 2; ks++) {
                int kp = ks * 8;
                uint32_t ah[2][4], al[2][4], bh[4][2], bl[4][2];
                #pragma unroll
                for (int f = 0; f < 2; f++) {
                    int mb = (mw + f*16 + r) * PB2 + kp + c;
                    int mb8 = mb + 8*PB2;
                    ah[f][0] = sAh[mb];     ah[f][1] = sAh[mb8];
                    ah[f][2] = sAh[mb + 4]; ah[f][3] = sAh[mb8 + 4];
                    al[f][0] = sAl[mb];     al[f][1] = sAl[mb8];
                    al[f][2] = sAl[mb + 4]; al[f][3] = sAl[mb8 + 4];
                }
                #pragma unroll
                for (int g = 0; g < 4; g++) {
                    int nb = (nw + g*8 + r) * PB2 + kp + c;
                    bh[g][0] = sBh[nb]; bh[g][1] = sBh[nb + 4];
                    bl[g][0] = sBl[nb]; bl[g][1] = sBl[nb + 4];
                }
                #pragma unroll
                for (int f = 0; f < 2; f++)
                    #pragma unroll
                    for (int g = 0; g < 4; g++) mma_bf16(acc[f][g], ah[f], bh[g]);
                #pragma unroll
                for (int f = 0; f < 2; f++)
                    #pragma unroll
                    for (int g = 0; g < 4; g++) mma_bf16(acc[f][g], al[f], bh[g]);
                #pragma unroll
                for (int f = 0; f < 2; f++)
                    #pragma unroll
                    for (int g = 0; g < 4; g++) mma_bf16(acc[f][g], ah[f], bl[g]);
            }
        }
        if (it + 1 < NT) sts_tile(buf ^ 1);
        __syncthreads();
    }

    #pragma unroll
    for (int g = 0; g < 4; g++) {
        int col = nw + g*8 + 2*c;
        float2 bv = *(const float2*)&bias[col];
        #pragma unroll
        for (int f = 0; f < 2; f++) {
            long row0 = m0 + mw + f*16 + r;
            float2 v0 = make_float2(acc[f][g][0] + bv.x, acc[f][g][1] + bv.y);
            float2 v1 = make_float2(acc[f][g][2] + bv.x, acc[f][g][3] + bv.y);
            *(float2*)&C[row0*HH + col]       = v0;
            *(float2*)&C[(row0 + 8)*HH + col] = v1;
        }
    }
}

// -------- gather + relu (layer 1; writes H1 for the layer-2 GEMM) --------
__global__ void __launch_bounds__(256) gather_relu_kernel(
    const float* __restrict__ Y, float* __restrict__ Out)
{
    int wid  = threadIdx.x >> 5, lane = threadIdx.x & 31;
    int dst  = blockIdx.x * 8 + wid;
    int t    = blockIdx.y;
    if (dst >= NN) return;
    const float* base = Y + t * NN * HH;
    float4 acc = *(const float4*)&base[dst * HH + lane * 4];
    int s   = g_start[t*NN + dst];
    int cnt = g_cnt  [t*NN + dst];
    const int* ep = g_eidx + t*EE + s;
    int i = 0;
    for (; i + 4 <= cnt; i += 4) {
        int s0 = ep[i], s1 = ep[i+1], s2 = ep[i+2], s3 = ep[i+3];
        float4 v0 = *(const float4*)&base[s0*HH + lane*4];
        float4 v1 = *(const float4*)&base[s1*HH + lane*4];
        float4 v2 = *(const float4*)&base[s2*HH + lane*4];
        float4 v3 = *(const float4*)&base[s3*HH + lane*4];
        acc.x += v0.x + v1.x + v2.x + v3.x;
        acc.y += v0.y + v1.y + v2.y + v3.y;
        acc.z += v0.z + v1.z + v2.z + v3.z;
        acc.w += v0.w + v1.w + v2.w + v3.w;
    }
    for (; i < cnt; i++) {
        int s0 = ep[i];
        float4 v = *(const float4*)&base[s0*HH + lane*4];
        acc.x += v.x; acc.y += v.y; acc.z += v.z; acc.w += v.w;
    }
    acc.x = fmaxf(acc.x, 0.f); acc.y = fmaxf(acc.y, 0.f);
    acc.z = fmaxf(acc.z, 0.f); acc.w = fmaxf(acc.w, 0.f);
    *(float4*)&Out[(t*NN + dst)*HH + lane*4] = acc;
}

// -------- gather + relu + MEAN POOL (layer 2; H2 never materialized) ------
__global__ void __launch_bounds__(256) gather_pool_kernel(
    const float* __restrict__ Y)
{
    __shared__ float sacc[8][HH];      // per-warp feature slabs (no conflicts)
    int wid  = threadIdx.x >> 5, lane = threadIdx.x & 31;
    int dst  = blockIdx.x * 8 + wid;
    int t    = blockIdx.y;
    const float* base = Y + t * NN * HH;

    float4 acc = *(const float4*)&base[dst * HH + lane * 4];
    int s   = g_start[t*NN + dst];
    int cnt = g_cnt  [t*NN + dst];
    const int* ep = g_eidx + t*EE + s;
    int i = 0;
    for (; i + 4 <= cnt; i += 4) {
        int s0 = ep[i], s1 = ep[i+1], s2 = ep[i+2], s3 = ep[i+3];
        float4 v0 = *(const float4*)&base[s0*HH + lane*4];
        float4 v1 = *(const float4*)&base[s1*HH + lane*4];
        float4 v2 = *(const float4*)&base[s2*HH + lane*4];
        float4 v3 = *(const float4*)&base[s3*HH + lane*4];
        acc.x += v0.x + v1.x + v2.x + v3.x;
        acc.y += v0.y + v1.y + v2.y + v3.y;
        acc.z += v0.z + v1.z + v2.z + v3.z;
        acc.w += v0.w + v1.w + v2.w + v3.w;
    }
    for (; i < cnt; i++) {
        int s0 = ep[i];
        float4 v = *(const float4*)&base[s0*HH + lane*4];
        acc.x += v.x; acc.y += v.y; acc.z += v.z; acc.w += v.w;
    }
    acc.x = fmaxf(acc.x, 0.f); acc.y = fmaxf(acc.y, 0.f);
    acc.z = fmaxf(acc.z, 0.f); acc.w = fmaxf(acc.w, 0.f);

    *(float4*)&sacc[wid][lane*4] = acc;     // each warp owns its slab
    __syncthreads();
    int tid = threadIdx.x;
    if (tid < HH) {
        float s8 = 0.f;
        #pragma unroll
        for (int w = 0; w < 8; w++) s8 += sacc[w][tid];
        atomicAdd(&g_pool[t*HH + tid], s8 * (1.f / NN));
    }
}

// -------- input-side LSTM gates --------
__global__ void __launch_bounds__(512) gx_kernel(
    const int* __restrict__ dok, const float* __restrict__ emb,
    const float* __restrict__ w_ih, const float* __restrict__ b_ih,
    const float* __restrict__ b_hh)
{
    __shared__ float sseq[HH + DD];
    int t = blockIdx.x, j = threadIdx.x;
    if (j < HH)            sseq[j] = g_pool[t*HH + j];
    else if (j < HH + DD)  sseq[j] = emb[dok[t]*DD + (j - HH)];
    __syncthreads();
    const float* wr = w_ih + j * (HH + DD);
    float a0 = b_ih[j] + b_hh[j], a1 = 0.f;
    #pragma unroll
    for (int k = 0; k < HH + DD; k += 2) {
        a0 += wr[k]   * sseq[k];
        a1 += wr[k+1] * sseq[k+1];
    }
    g_Gx[t*G4 + j] = a0 + a1;
}

// ---------------- sequential LSTM + final FC (R8 scalar, proven) ----------
#define SPITCH 68
__global__ void __launch_bounds__(512) lstm_kernel(
    const float* __restrict__ w_hh, const float* __restrict__ w_fc,
    const float* __restrict__ b_fc, float* __restrict__ out)
{
    extern __shared__ float sm[];
    float* sW   = sm;                  // 512*68
    float* sh   = sW + G4*SPITCH;      // 128
    float* sg   = sh + HH;             // 512
    float* sred = sg + G4;             // 32

    int tid = threadIdx.x;

    float4 rw[16];
    const float4* wg4 = (const float4*)(w_hh + tid * HH);
    #pragma unroll
    for (int i = 0; i < 16; i++) rw[i] = wg4[i];          // cols 0..63

    for (int i = tid; i < G4 * 64; i += 512) {            // cols 64..127
        int r = i >> 6, c = i & 63;
        sW[r*SPITCH + c] = w_hh[r*HH + 64 + c];
    }
    if (tid < HH) sh[tid] = 0.f;
    float c_state = 0.f;
    float wfc = (tid < HH) ? w_fc[tid] : 0.f;
    float bfc = b_fc[0];
    __syncthreads();

    const float4* wr4 = (const float4*)(sW + tid * SPITCH);

    for (int t = 0; t < TT; t++) {
        const float4* sh4 = (const float4*)sh;
        float a0 = 0, a1 = 0, a2 = 0, a3 = 0;
        #pragma unroll
        for (int k = 0; k < 16; k++) {
            float4 hv = sh4[k]; float4 w = rw[k];
            a0 += w.x*hv.x; a1 += w.y*hv.y; a2 += w.z*hv.z; a3 += w.w*hv.w;
        }
        #pragma unroll
        for (int k = 0; k < 16; k++) {
            float4 hv = sh4[16 + k]; float4 w = wr4[k];
            a0 += w.x*hv.x; a1 += w.y*hv.y; a2 += w.z*hv.z; a3 += w.w*hv.w;
        }
        sg[tid] = g_Gx[t*G4 + tid] + (a0 + a1) + (a2 + a3);
        __syncthreads();
        if (tid < HH) {
            float ig = 1.f / (1.f + expf(-sg[tid]));
            float fg = 1.f / (1.f + expf(-sg[tid + HH]));
            float gg = tanhf(sg[tid + 2*HH]);
            float og = 1.f / (1.f + expf(-sg[tid + 3*HH]));
            c_state = fg * c_state + ig * gg;
            float h = og * tanhf(c_state);
            sh[tid] = h;
            float p = h * wfc;
            #pragma unroll
            for (int o = 16; o > 0; o >>= 1) p += __shfl_down_sync(0xffffffffu, p, o);
            if ((tid & 31) == 0) sred[tid >> 5] = p;
        }
        __syncthreads();
        if (tid == 0) out[t] = sred[0] + sred[1] + sred[2] + sred[3] + bfc;
    }
}

// ---------------- launch ----------------
extern "C" void kernel_launch(void* const* d_in, const int* in_sizes, int n_in,
                              void* d_out, int out_size)
{
    const float* x    = (const float*)d_in[0];
    const int*   ei   = (const int*)  d_in[1];
    const int*   dok  = (const int*)  d_in[2];
    const float* w1   = (const float*)d_in[3];
    const float* b1   = (const float*)d_in[4];
    const float* w2   = (const float*)d_in[5];
    const float* b2   = (const float*)d_in[6];
    const float* emb  = (const float*)d_in[7];
    const float* w_ih = (const float*)d_in[8];
    const float* w_hh = (const float*)d_in[9];
    const float* b_ih = (const float*)d_in[10];
    const float* b_hh = (const float*)d_in[11];
    const float* w_fc = (const float*)d_in[12];
    const float* b_fc = (const float*)d_in[13];
    float* out = (float*)d_out;

    float *pY, *pH1;
    uint32_t *pW1h, *pW1l, *pW2h, *pW2l;
    cudaGetSymbolAddress((void**)&pY,   g_Y);
    cudaGetSymbolAddress((void**)&pH1,  g_H1);
    cudaGetSymbolAddress((void**)&pW1h, g_W1h);
    cudaGetSymbolAddress((void**)&pW1l, g_W1l);
    cudaGetSymbolAddress((void**)&pW2h, g_W2h);
    cudaGetSymbolAddress((void**)&pW2l, g_W2l);

    // W pre-split + fused CSR build (with pool zeroing)
    wsplit_kernel<<<(HH*KP1/2 + 255)/256, 256>>>(w1, pW1h, pW1l, FF, KP1);
    wsplit_kernel<<<(HH*KP2/2 + 255)/256, 256>>>(w2, pW2h, pW2l, HH, KP2);
    csr_kernel<<<TT, 1024>>>(ei);

    size_t gsm = (size_t)(2*BUFU) * sizeof(uint32_t);   // 81920 B
    cudaFuncSetAttribute(gemm_mma_kernel, cudaFuncAttributeMaxDynamicSharedMemorySize, (int)gsm);

    // GIN layer 1: y = x@w1^T + b1 ; h1 = relu(y[dst] + sum y[src])
    gemm_mma_kernel<<<TT*NN/BM, 512, gsm>>>(x, pW1h, pW1l, b1, pY, FF, KP1);
    dim3 gg((NN + 7)/8, TT);
    gather_relu_kernel<<<gg, 256>>>(pY, pH1);

    // GIN layer 2: gather fused with mean pool; H2 never written
    gemm_mma_kernel<<<TT*NN/BM, 512, gsm>>>(pH1, pW2h, pW2l, b2, pY, HH, KP2);
    gather_pool_kernel<<<gg, 256>>>(pY);

    // LSTM input gates, sequential LSTM + FC
    gx_kernel<<<TT, 512>>>(dok, emb, w_ih, b_ih, b_hh);

    size_t lsm = (size_t)(G4*SPITCH + HH + G4 + 32) * sizeof(float);
    cudaFuncSetAttribute(lstm_kernel, cudaFuncAttributeMaxDynamicSharedMemorySize, (int)lsm);
    lstm_kernel<<<1, 512, lsm>>>(w_hh, w_fc, b_fc, out);
}

// round 15
// speedup vs baseline: 1.0704x; 1.0704x over previous
#include <cuda_runtime.h>
#include <math.h>
#include <stdint.h>

#define TT 128
#define NN 1000
#define EE 16000
#define FF 397
#define HH 128
#define H2U 64   // u32 per row (bf16x2 packed)
#define DD 8
#define G4 512   // 4*HH
#define BM 128
#define BKT 32   // K per tile
#define PB2 20   // smem pitch in u32 (bf16 pairs): bank = (4r+c)%32, conflict-free
#define TPB2 (128*PB2)       // u32 per tile array
#define BUFU3 (4*TPB2)       // stage for 3-term gemm (Ah,Al,Bh,Bl)
#define BUFU2 (3*TPB2)       // stage for 2-term gemm (Ah,Bh,Bl)
#define KP1 416
#define KP2 128

// ---- static scratch (allocation-free rule: __device__ globals) ----
__device__ uint32_t g_Yb [TT*NN*H2U];   // bf16x2 GEMM output (reused layer1/2)
__device__ uint32_t g_H1b[TT*NN*H2U];   // bf16x2 gather1 output
__device__ int   g_cnt  [TT*NN];
__device__ int   g_start[TT*NN];
__device__ int   g_eidx [TT*EE];
__device__ float g_pool [TT*HH];
__device__ float g_Gx   [TT*G4];
__device__ uint32_t g_W1h[HH*KP1/2], g_W1l[HH*KP1/2];
__device__ uint32_t g_W2h[HH*KP2/2], g_W2l[HH*KP2/2];

// ---- helpers ----
__device__ __forceinline__ uint32_t bf16x2_pack(float lo, float hi) {
    uint32_t r;
    asm("cvt.rn.bf16x2.f32 %0, %1, %2;" : "=r"(r) : "f"(hi), "f"(lo));
    return r;
}
// bf16 -> f32 exact
__device__ __forceinline__ float bf_lo_f(uint32_t p) { return __uint_as_float(p << 16); }
__device__ __forceinline__ float bf_hi_f(uint32_t p) { return __uint_as_float(p & 0xFFFF0000u); }

__device__ __forceinline__ void mma_bf16(float* d, const uint32_t* a, const uint32_t* b) {
    asm volatile("mma.sync.aligned.m16n8k16.row.col.f32.bf16.bf16.f32 "
                 "{%0,%1,%2,%3}, {%4,%5,%6,%7}, {%8,%9}, {%0,%1,%2,%3};"
                 : "+f"(d[0]), "+f"(d[1]), "+f"(d[2]), "+f"(d[3])
                 : "r"(a[0]), "r"(a[1]), "r"(a[2]), "r"(a[3]),
                   "r"(b[0]), "r"(b[1]));
}

// ---------------- W pre-split: fp32 -> bf16 hi/lo pairs ----------------
__global__ void wsplit_kernel(const float* __restrict__ w, uint32_t* __restrict__ wh,
                              uint32_t* __restrict__ wl, int K, int Kpad) {
    int P2 = Kpad >> 1;
    int i = blockIdx.x*blockDim.x + threadIdx.x;
    if (i >= HH*P2) return;
    int r = i / P2, p = i - r*P2;
    int k0 = 2*p;
    float x0 = (k0     < K) ? w[r*K + k0]     : 0.f;
    float x1 = (k0 + 1 < K) ? w[r*K + k0 + 1] : 0.f;
    uint32_t h = bf16x2_pack(x0, x1);
    wh[i] = h;
    wl[i] = bf16x2_pack(x0 - bf_lo_f(h), x1 - bf_hi_f(h));
}

// ---------------- fused CSR build + g_pool zero ----------------
__global__ void __launch_bounds__(1024) csr_kernel(const int* __restrict__ ei) {
    __shared__ int scnt[1024];
    __shared__ int sscan[1024];
    int t = blockIdx.x, tid = threadIdx.x;
    scnt[tid] = 0;
    if (tid < HH) g_pool[t*HH + tid] = 0.f;
    __syncthreads();
    const int* srcp = ei + t*2*EE;
    const int* dstp = srcp + EE;
    for (int e = tid; e < EE; e += 1024) atomicAdd(&scnt[dstp[e]], 1);
    __syncthreads();
    int v = scnt[tid];
    sscan[tid] = v;
    __syncthreads();
    for (int off = 1; off < 1024; off <<= 1) {
        int u = (tid >= off) ? sscan[tid - off] : 0;
        __syncthreads();
        sscan[tid] += u;
        __syncthreads();
    }
    int start = sscan[tid] - v;
    if (tid < NN) { g_start[t*NN + tid] = start; g_cnt[t*NN + tid] = v; }
    __syncthreads();
    scnt[tid] = start;
    __syncthreads();
    int* eix = g_eidx + t*EE;
    for (int e = tid; e < EE; e += 1024) {
        int d = dstp[e], s = srcp[e];
        int pos = atomicAdd(&scnt[d], 1);
        eix[pos] = s;
    }
}

// ==== GEMM1 (3-term bf16 split, A fp32): C(bf16x2) = A @ W^T + bias ====
__global__ void __launch_bounds__(512, 1) gemm_mma_kernel(
    const float* __restrict__ A, const uint32_t* __restrict__ Wh,
    const uint32_t* __restrict__ Wl, const float* __restrict__ bias,
    uint32_t* __restrict__ C, int K, int Kpad)
{
    extern __shared__ uint32_t smu[];
    int tid = threadIdx.x;
    int lane = tid & 31, wid = tid >> 5;
    long m0 = (long)blockIdx.x * BM;

    int mw = (wid & 3) * 32;
    int nw = (wid >> 2) * 32;
    int r = lane >> 2, c = lane & 3;

    float acc[2][4][4];
    #pragma unroll
    for (int f = 0; f < 2; f++)
        #pragma unroll
        for (int g = 0; g < 4; g++)
            #pragma unroll
            for (int e = 0; e < 4; e++) acc[f][g][e] = 0.f;

    int srow = tid >> 2, skq = (tid & 3) * 8;
    const float* Arow = A + (m0 + srow) * (long)K;
    int P2 = Kpad >> 1;
    const uint32_t* Bh_row = Wh + srow * P2;
    const uint32_t* Bl_row = Wl + srow * P2;

    int NT = (Kpad + BKT - 1) / BKT;
    float rA[8];
    uint32_t rBh[4], rBl[4];

    auto ldg_tile = [&](int it) {
        int k0 = it * BKT;
        #pragma unroll
        for (int j = 0; j < 8; j++) {
            int k = k0 + skq + j;
            rA[j] = (k < K) ? Arow[k] : 0.f;
        }
        int bidx = (k0 >> 1) + (skq >> 1);
        #pragma unroll
        for (int j = 0; j < 4; j++) {
            rBh[j] = Bh_row[bidx + j];
            rBl[j] = Bl_row[bidx + j];
        }
    };
    auto sts_tile = [&](int buf) {
        uint32_t* sAh = smu + buf*BUFU3;
        uint32_t* sAl = sAh + TPB2;
        uint32_t* sBh = sAh + 2*TPB2;
        uint32_t* sBl = sAh + 3*TPB2;
        uint32_t ha[4], la[4];
        #pragma unroll
        for (int j = 0; j < 4; j++) {
            float x0 = rA[2*j], x1 = rA[2*j+1];
            uint32_t h = bf16x2_pack(x0, x1);
            ha[j] = h;
            la[j] = bf16x2_pack(x0 - bf_lo_f(h), x1 - bf_hi_f(h));
        }
        int so = srow*PB2 + (skq >> 1);
        *(uint4*)&sAh[so] = *(uint4*)ha;
        *(uint4*)&sAl[so] = *(uint4*)la;
        *(uint4*)&sBh[so] = *(uint4*)rBh;
        *(uint4*)&sBl[so] = *(uint4*)rBl;
    };

    ldg_tile(0);
    sts_tile(0);
    __syncthreads();

    for (int it = 0; it < NT; it++) {
        int buf = it & 1;
        if (it + 1 < NT) ldg_tile(it + 1);
        {
            const uint32_t* sAh = smu + buf*BUFU3;
            const uint32_t* sAl = sAh + TPB2;
            const uint32_t* sBh = sAh + 2*TPB2;
            const uint32_t* sBl = sAh + 3*TPB2;
            #pragma unroll
            for (int ks = 0; ks < 2; ks++) {
                int kp = ks * 8;
                uint32_t ah[2][4], al[2][4], bh[4][2], bl[4][2];
                #pragma unroll
                for (int f = 0; f < 2; f++) {
                    int mb = (mw + f*16 + r) * PB2 + kp + c;
                    int mb8 = mb + 8*PB2;
                    ah[f][0] = sAh[mb];     ah[f][1] = sAh[mb8];
                    ah[f][2] = sAh[mb + 4]; ah[f][3] = sAh[mb8 + 4];
                    al[f][0] = sAl[mb];     al[f][1] = sAl[mb8];
                    al[f][2] = sAl[mb + 4]; al[f][3] = sAl[mb8 + 4];
                }
                #pragma unroll
                for (int g = 0; g < 4; g++) {
                    int nb = (nw + g*8 + r) * PB2 + kp + c;
                    bh[g][0] = sBh[nb]; bh[g][1] = sBh[nb + 4];
                    bl[g][0] = sBl[nb]; bl[g][1] = sBl[nb + 4];
                }
                #pragma unroll
                for (int f = 0; f < 2; f++)
                    #pragma unroll
                    for (int g = 0; g < 4; g++) mma_bf16(acc[f][g], ah[f], bh[g]);
                #pragma unroll
                for (int f = 0; f < 2; f++)
                    #pragma unroll
                    for (int g = 0; g < 4; g++) mma_bf16(acc[f][g], al[f], bh[g]);
                #pragma unroll
                for (int f = 0; f < 2; f++)
                    #pragma unroll
                    for (int g = 0; g < 4; g++) mma_bf16(acc[f][g], ah[f], bl[g]);
            }
        }
        if (it + 1 < NT) sts_tile(buf ^ 1);
        __syncthreads();
    }

    // epilogue: pack (col, col+1) -> one u32
    #pragma unroll
    for (int g = 0; g < 4; g++) {
        int col = nw + g*8 + 2*c;
        float2 bv = *(const float2*)&bias[col];
        int cu = col >> 1;
        #pragma unroll
        for (int f = 0; f < 2; f++) {
            long row0 = m0 + mw + f*16 + r;
            C[row0*H2U + cu]       = bf16x2_pack(acc[f][g][0] + bv.x, acc[f][g][1] + bv.y);
            C[(row0 + 8)*H2U + cu] = bf16x2_pack(acc[f][g][2] + bv.x, acc[f][g][3] + bv.y);
        }
    }
}

// ==== GEMM2 (2-term: A already bf16x2): C(bf16x2) = A @ W^T + bias ====
__global__ void __launch_bounds__(512, 1) gemm_mma_a16_kernel(
    const uint32_t* __restrict__ Au, const uint32_t* __restrict__ Wh,
    const uint32_t* __restrict__ Wl, const float* __restrict__ bias,
    uint32_t* __restrict__ C, int Kpad)
{
    extern __shared__ uint32_t smu[];
    int tid = threadIdx.x;
    int lane = tid & 31, wid = tid >> 5;
    long m0 = (long)blockIdx.x * BM;

    int mw = (wid & 3) * 32;
    int nw = (wid >> 2) * 32;
    int r = lane >> 2, c = lane & 3;

    float acc[2][4][4];
    #pragma unroll
    for (int f = 0; f < 2; f++)
        #pragma unroll
        for (int g = 0; g < 4; g++)
            #pragma unroll
            for (int e = 0; e < 4; e++) acc[f][g][e] = 0.f;

    int srow = tid >> 2, skq = (tid & 3) * 8;
    int P2 = Kpad >> 1;
    const uint32_t* Arow = Au + (m0 + srow) * (long)P2;
    const uint32_t* Bh_row = Wh + srow * P2;
    const uint32_t* Bl_row = Wl + srow * P2;

    int NT = Kpad / BKT;
    uint32_t rAu[4], rBh[4], rBl[4];

    auto ldg_tile = [&](int it) {
        int bidx = it*(BKT/2) + (skq >> 1);
        #pragma unroll
        for (int j = 0; j < 4; j++) {
            rAu[j] = Arow[bidx + j];
            rBh[j] = Bh_row[bidx + j];
            rBl[j] = Bl_row[bidx + j];
        }
    };
    auto sts_tile = [&](int buf) {
        uint32_t* sAh = smu + buf*BUFU2;
        uint32_t* sBh = sAh + TPB2;
        uint32_t* sBl = sAh + 2*TPB2;
        int so = srow*PB2 + (skq >> 1);
        *(uint4*)&sAh[so] = *(uint4*)rAu;
        *(uint4*)&sBh[so] = *(uint4*)rBh;
        *(uint4*)&sBl[so] = *(uint4*)rBl;
    };

    ldg_tile(0);
    sts_tile(0);
    __syncthreads();

    for (int it = 0; it < NT; it++) {
        int buf = it & 1;
        if (it + 1 < NT) ldg_tile(it + 1);
        {
            const uint32_t* sAh = smu + buf*BUFU2;
            const uint32_t* sBh = sAh + TPB2;
            const uint32_t* sBl = sAh + 2*TPB2;
            #pragma unroll
            for (int ks = 0; ks < 2; ks++) {
                int kp = ks * 8;
                uint32_t ah[2][4], bh[4][2], bl[4][2];
                #pragma unroll
                for (int f = 0; f < 2; f++) {
                    int mb = (mw + f*16 + r) * PB2 + kp + c;
                    int mb8 = mb + 8*PB2;
                    ah[f][0] = sAh[mb];     ah[f][1] = sAh[mb8];
                    ah[f][2] = sAh[mb + 4]; ah[f][3] = sAh[mb8 + 4];
                }
                #pragma unroll
                for (int g = 0; g < 4; g++) {
                    int nb = (nw + g*8 + r) * PB2 + kp + c;
                    bh[g][0] = sBh[nb]; bh[g][1] = sBh[nb + 4];
                    bl[g][0] = sBl[nb]; bl[g][1] = sBl[nb + 4];
                }
                #pragma unroll
                for (int f = 0; f < 2; f++)
                    #pragma unroll
                    for (int g = 0; g < 4; g++) mma_bf16(acc[f][g], ah[f], bh[g]);
                #pragma unroll
                for (int f = 0; f < 2; f++)
                    #pragma unroll
                    for (int g = 0; g < 4; g++) mma_bf16(acc[f][g], ah[f], bl[g]);
            }
        }
        if (it + 1 < NT) sts_tile(buf ^ 1);
        __syncthreads();
    }

    #pragma unroll
    for (int g = 0; g < 4; g++) {
        int col = nw + g*8 + 2*c;
        float2 bv = *(const float2*)&bias[col];
        int cu = col >> 1;
        #pragma unroll
        for (int f = 0; f < 2; f++) {
            long row0 = m0 + mw + f*16 + r;
            C[row0*H2U + cu]       = bf16x2_pack(acc[f][g][0] + bv.x, acc[f][g][1] + bv.y);
            C[(row0 + 8)*H2U + cu] = bf16x2_pack(acc[f][g][2] + bv.x, acc[f][g][3] + bv.y);
        }
    }
}

// -------- gather + relu (bf16 in / bf16 out), warp per dst --------
__global__ void __launch_bounds__(256) gather_relu_kernel(
    const uint32_t* __restrict__ Y, uint32_t* __restrict__ Out)
{
    int wid  = threadIdx.x >> 5, lane = threadIdx.x & 31;
    int dst  = blockIdx.x * 8 + wid;
    int t    = blockIdx.y;
    if (dst >= NN) return;
    const uint32_t* base = Y + (long)t * NN * H2U;
    uint2 sv = *(const uint2*)&base[dst * H2U + lane * 2];
    float a0 = bf_lo_f(sv.x), a1 = bf_hi_f(sv.x);
    float a2 = bf_lo_f(sv.y), a3 = bf_hi_f(sv.y);
    int s   = g_start[t*NN + dst];
    int cnt = g_cnt  [t*NN + dst];
    const int* ep = g_eidx + t*EE + s;
    int i = 0;
    for (; i + 4 <= cnt; i += 4) {
        int s0 = ep[i], s1 = ep[i+1], s2 = ep[i+2], s3 = ep[i+3];
        uint2 v0 = *(const uint2*)&base[s0*H2U + lane*2];
        uint2 v1 = *(const uint2*)&base[s1*H2U + lane*2];
        uint2 v2 = *(const uint2*)&base[s2*H2U + lane*2];
        uint2 v3 = *(const uint2*)&base[s3*H2U + lane*2];
        a0 += (bf_lo_f(v0.x) + bf_lo_f(v1.x)) + (bf_lo_f(v2.x) + bf_lo_f(v3.x));
        a1 += (bf_hi_f(v0.x) + bf_hi_f(v1.x)) + (bf_hi_f(v2.x) + bf_hi_f(v3.x));
        a2 += (bf_lo_f(v0.y) + bf_lo_f(v1.y)) + (bf_lo_f(v2.y) + bf_lo_f(v3.y));
        a3 += (bf_hi_f(v0.y) + bf_hi_f(v1.y)) + (bf_hi_f(v2.y) + bf_hi_f(v3.y));
    }
    for (; i < cnt; i++) {
        uint2 v = *(const uint2*)&base[ep[i]*H2U + lane*2];
        a0 += bf_lo_f(v.x); a1 += bf_hi_f(v.x);
        a2 += bf_lo_f(v.y); a3 += bf_hi_f(v.y);
    }
    uint2 o;
    o.x = bf16x2_pack(fmaxf(a0, 0.f), fmaxf(a1, 0.f));
    o.y = bf16x2_pack(fmaxf(a2, 0.f), fmaxf(a3, 0.f));
    *(uint2*)&Out[((long)t*NN + dst)*H2U + lane*2] = o;
}

// -------- gather + relu + MEAN POOL (layer 2; H2 never materialized) ------
__global__ void __launch_bounds__(256) gather_pool_kernel(
    const uint32_t* __restrict__ Y)
{
    __shared__ float sacc[8][HH];
    int wid  = threadIdx.x >> 5, lane = threadIdx.x & 31;
    int dst  = blockIdx.x * 8 + wid;
    int t    = blockIdx.y;
    const uint32_t* base = Y + (long)t * NN * H2U;

    uint2 sv = *(const uint2*)&base[dst * H2U + lane * 2];
    float a0 = bf_lo_f(sv.x), a1 = bf_hi_f(sv.x);
    float a2 = bf_lo_f(sv.y), a3 = bf_hi_f(sv.y);
    int s   = g_start[t*NN + dst];
    int cnt = g_cnt  [t*NN + dst];
    const int* ep = g_eidx + t*EE + s;
    int i = 0;
    for (; i + 4 <= cnt; i += 4) {
        int s0 = ep[i], s1 = ep[i+1], s2 = ep[i+2], s3 = ep[i+3];
        uint2 v0 = *(const uint2*)&base[s0*H2U + lane*2];
        uint2 v1 = *(const uint2*)&base[s1*H2U + lane*2];
        uint2 v2 = *(const uint2*)&base[s2*H2U + lane*2];
        uint2 v3 = *(const uint2*)&base[s3*H2U + lane*2];
        a0 += (bf_lo_f(v0.x) + bf_lo_f(v1.x)) + (bf_lo_f(v2.x) + bf_lo_f(v3.x));
        a1 += (bf_hi_f(v0.x) + bf_hi_f(v1.x)) + (bf_hi_f(v2.x) + bf_hi_f(v3.x));
        a2 += (bf_lo_f(v0.y) + bf_lo_f(v1.y)) + (bf_lo_f(v2.y) + bf_lo_f(v3.y));
        a3 += (bf_hi_f(v0.y) + bf_hi_f(v1.y)) + (bf_hi_f(v2.y) + bf_hi_f(v3.y));
    }
    for (; i < cnt; i++) {
        uint2 v = *(const uint2*)&base[ep[i]*H2U + lane*2];
        a0 += bf_lo_f(v.x); a1 += bf_hi_f(v.x);
        a2 += bf_lo_f(v.y); a3 += bf_hi_f(v.y);
    }
    float4 acc = make_float4(fmaxf(a0,0.f), fmaxf(a1,0.f), fmaxf(a2,0.f), fmaxf(a3,0.f));
    *(float4*)&sacc[wid][lane*4] = acc;
    __syncthreads();
    int tid = threadIdx.x;
    if (tid < HH) {
        float s8 = 0.f;
        #pragma unroll
        for (int w = 0; w < 8; w++) s8 += sacc[w][tid];
        atomicAdd(&g_pool[t*HH + tid], s8 * (1.f / NN));
    }
}

// -------- input-side LSTM gates --------
__global__ void __launch_bounds__(512) gx_kernel(
    const int* __restrict__ dok, const float* __restrict__ emb,
    const float* __restrict__ w_ih, const float* __restrict__ b_ih,
    const float* __restrict__ b_hh)
{
    __shared__ float sseq[HH + DD];
    int t = blockIdx.x, j = threadIdx.x;
    if (j < HH)            sseq[j] = g_pool[t*HH + j];
    else if (j < HH + DD)  sseq[j] = emb[dok[t]*DD + (j - HH)];
    __syncthreads();
    const float* wr = w_ih + j * (HH + DD);
    float a0 = b_ih[j] + b_hh[j], a1 = 0.f;
    #pragma unroll
    for (int k = 0; k < HH + DD; k += 2) {
        a0 += wr[k]   * sseq[k];
        a1 += wr[k+1] * sseq[k+1];
    }
    g_Gx[t*G4 + j] = a0 + a1;
}

// ---------------- sequential LSTM + final FC (R8 scalar, proven) ----------
#define SPITCH 68
__global__ void __launch_bounds__(512) lstm_kernel(
    const float* __restrict__ w_hh, const float* __restrict__ w_fc,
    const float* __restrict__ b_fc, float* __restrict__ out)
{
    extern __shared__ float sm[];
    float* sW   = sm;
    float* sh   = sW + G4*SPITCH;
    float* sg   = sh + HH;
    float* sred = sg + G4;

    int tid = threadIdx.x;

    float4 rw[16];
    const float4* wg4 = (const float4*)(w_hh + tid * HH);
    #pragma unroll
    for (int i = 0; i < 16; i++) rw[i] = wg4[i];

    for (int i = tid; i < G4 * 64; i += 512) {
        int r = i >> 6, c = i & 63;
        sW[r*SPITCH + c] = w_hh[r*HH + 64 + c];
    }
    if (tid < HH) sh[tid] = 0.f;
    float c_state = 0.f;
    float wfc = (tid < HH) ? w_fc[tid] : 0.f;
    float bfc = b_fc[0];
    __syncthreads();

    const float4* wr4 = (const float4*)(sW + tid * SPITCH);

    for (int t = 0; t < TT; t++) {
        const float4* sh4 = (const float4*)sh;
        float a0 = 0, a1 = 0, a2 = 0, a3 = 0;
        #pragma unroll
        for (int k = 0; k < 16; k++) {
            float4 hv = sh4[k]; float4 w = rw[k];
            a0 += w.x*hv.x; a1 += w.y*hv.y; a2 += w.z*hv.z; a3 += w.w*hv.w;
        }
        #pragma unroll
        for (int k = 0; k < 16; k++) {
            float4 hv = sh4[16 + k]; float4 w = wr4[k];
            a0 += w.x*hv.x; a1 += w.y*hv.y; a2 += w.z*hv.z; a3 += w.w*hv.w;
        }
        sg[tid] = g_Gx[t*G4 + tid] + (a0 + a1) + (a2 + a3);
        __syncthreads();
        if (tid < HH) {
            float ig = 1.f / (1.f + expf(-sg[tid]));
            float fg = 1.f / (1.f + expf(-sg[tid + HH]));
            float gg = tanhf(sg[tid + 2*HH]);
            float og = 1.f / (1.f + expf(-sg[tid + 3*HH]));
            c_state = fg * c_state + ig * gg;
            float h = og * tanhf(c_state);
            sh[tid] = h;
            float p = h * wfc;
            #pragma unroll
            for (int o = 16; o > 0; o >>= 1) p += __shfl_down_sync(0xffffffffu, p, o);
            if ((tid & 31) == 0) sred[tid >> 5] = p;
        }
        __syncthreads();
        if (tid == 0) out[t] = sred[0] + sred[1] + sred[2] + sred[3] + bfc;
    }
}

// ---------------- launch ----------------
extern "C" void kernel_launch(void* const* d_in, const int* in_sizes, int n_in,
                              void* d_out, int out_size)
{
    const float* x    = (const float*)d_in[0];
    const int*   ei   = (const int*)  d_in[1];
    const int*   dok  = (const int*)  d_in[2];
    const float* w1   = (const float*)d_in[3];
    const float* b1   = (const float*)d_in[4];
    const float* w2   = (const float*)d_in[5];
    const float* b2   = (const float*)d_in[6];
    const float* emb  = (const float*)d_in[7];
    const float* w_ih = (const float*)d_in[8];
    const float* w_hh = (const float*)d_in[9];
    const float* b_ih = (const float*)d_in[10];
    const float* b_hh = (const float*)d_in[11];
    const float* w_fc = (const float*)d_in[12];
    const float* b_fc = (const float*)d_in[13];
    float* out = (float*)d_out;

    uint32_t *pYb, *pH1b, *pW1h, *pW1l, *pW2h, *pW2l;
    cudaGetSymbolAddress((void**)&pYb,  g_Yb);
    cudaGetSymbolAddress((void**)&pH1b, g_H1b);
    cudaGetSymbolAddress((void**)&pW1h, g_W1h);
    cudaGetSymbolAddress((void**)&pW1l, g_W1l);
    cudaGetSymbolAddress((void**)&pW2h, g_W2h);
    cudaGetSymbolAddress((void**)&pW2l, g_W2l);

    // W pre-split + fused CSR build (with pool zeroing)
    wsplit_kernel<<<(HH*KP1/2 + 255)/256, 256>>>(w1, pW1h, pW1l, FF, KP1);
    wsplit_kernel<<<(HH*KP2/2 + 255)/256, 256>>>(w2, pW2h, pW2l, HH, KP2);
    csr_kernel<<<TT, 1024>>>(ei);

    size_t gsm3 = (size_t)(2*BUFU3) * sizeof(uint32_t);   // 81920 B
    size_t gsm2 = (size_t)(2*BUFU2) * sizeof(uint32_t);   // 61440 B
    cudaFuncSetAttribute(gemm_mma_kernel,     cudaFuncAttributeMaxDynamicSharedMemorySize, (int)gsm3);
    cudaFuncSetAttribute(gemm_mma_a16_kernel, cudaFuncAttributeMaxDynamicSharedMemorySize, (int)gsm2);

    // GIN layer 1: y = x@w1^T + b1 (bf16x2 out) ; h1 = relu(y[dst] + sum y[src])
    gemm_mma_kernel<<<TT*NN/BM, 512, gsm3>>>(x, pW1h, pW1l, b1, pYb, FF, KP1);
    dim3 gg((NN + 7)/8, TT);
    gather_relu_kernel<<<gg, 256>>>(pYb, pH1b);

    // GIN layer 2: A already bf16 (2-term GEMM); gather fused with mean pool
    gemm_mma_a16_kernel<<<TT*NN/BM, 512, gsm2>>>(pH1b, pW2h, pW2l, b2, pYb, KP2);
    gather_pool_kernel<<<gg, 256>>>(pYb);

    // LSTM input gates, sequential LSTM + FC
    gx_kernel<<<TT, 512>>>(dok, emb, w_ih, b_ih, b_hh);

    size_t lsm = (size_t)(G4*SPITCH + HH + G4 + 32) * sizeof(float);
    cudaFuncSetAttribute(lstm_kernel, cudaFuncAttributeMaxDynamicSharedMemorySize, (int)lsm);
    lstm_kernel<<<1, 512, lsm>>>(w_hh, w_fc, b_fc, out);
}